// round 17
// baseline (speedup 1.0000x reference)
#include <cuda_runtime.h>
#include <cuda_bf16.h>

#define EPS   1e-6f
#define LN2   0.6931471805599453f
#define RROWS 51   // 255 = 5 * 51 -> uniform trip count
#define OUTW  31   // outputs per warp (warps overlap by 1 column)

__device__ __forceinline__ float fast_rcp(float a) {
    float r;
    asm("rcp.approx.f32 %0, %1;" : "=f"(r) : "f"(a));
    return r;
}

// One pixel column per lane: one log per pixel, neighbor v/l via shfl.
__device__ __forceinline__ void row_h(float v, float& hv, float& hl)
{
    float l  = v * __log2f(v + EPS);
    float vn = __shfl_down_sync(0xffffffffu, v, 1);
    float ln = __shfl_down_sync(0xffffffffu, l, 1);
    hv = v + vn;
    hl = l + ln;
}

__device__ __forceinline__ void emit(float hv_p, float hl_p, float hv, float hl,
                                     float* po, bool ok)
{
    float s  = hv_p + hv;                 // 2x2 window sum
    float sl = hl_p + hl;                 // sum of w*lg2(w+eps)
    float S  = s + EPS;
    float e  = fmaf(s, __log2f(S), -sl) * fast_rcp(S) * LN2;
    if (ok) __stcs(po, e);                // predicated, no branch
}

__global__ __launch_bounds__(288)
void entropy2x2_k12(const float* __restrict__ x, float* __restrict__ out)
{
    const int lane  = threadIdx.x & 31;
    const int warp  = threadIdx.x >> 5;        // 0..8
    const int plane = blockIdx.z;              // 0..511
    const int oc    = warp * OUTW + lane;      // output col, 0..278
    const int lc    = min(oc, 255);            // clamped load col (coalesced)
    const int yBase = blockIdx.y * RROWS;      // 0,51,102,153,204

    const float* __restrict__ p  = x   + (size_t)plane * (256 * 256)
                                       + (size_t)yBase * 256 + lc;
    float*       __restrict__ po = out + (size_t)plane * (255 * 255)
                                       + (size_t)yBase * 255 + oc;

    const bool ok = (lane < OUTW) && (oc < 255);

    // ---- prime row yBase; TWO rows prefetched (depth-2) ----
    float v  = p[0];                           p += 256;
    float va = p[0];                           p += 256;   // in flight
    float vb = p[0];                           p += 256;   // in flight

    float hv_p, hl_p;
    row_h(v, hv_p, hl_p);

    // ---- main loop: 49 iterations; two loads always outstanding ----
    #pragma unroll 5
    for (int r = 0; r < RROWS - 2; r++) {
        float vc = va;
        va = vb;
        vb = p[0];                             p += 256;   // prefetch row r+3

        float hv, hl;
        row_h(vc, hv, hl);
        emit(hv_p, hl_p, hv, hl, po, ok);

        hv_p = hv;
        hl_p = hl;
        po += 255;
    }

    // ---- peeled tail: consume va then vb, no further loads ----
    {
        float hv, hl;
        row_h(va, hv, hl);
        emit(hv_p, hl_p, hv, hl, po, ok);
        hv_p = hv; hl_p = hl;
        po += 255;
    }
    {
        float hv, hl;
        row_h(vb, hv, hl);
        emit(hv_p, hl_p, hv, hl, po, ok);
    }
}

extern "C" void kernel_launch(void* const* d_in, const int* in_sizes, int n_in,
                              void* d_out, int out_size)
{
    const float* x = (const float*)d_in[0];
    float* out = (float*)d_out;

    // 9 warps x 31 output cols = 279 >= 255; 5 row-strips of 51 cover 255 rows.
    dim3 block(288);
    dim3 grid(1, 5, 512);
    entropy2x2_k12<<<grid, block>>>(x, out);
}